// round 14
// baseline (speedup 1.0000x reference)
#include <cuda_runtime.h>
#include <cuda_fp16.h>
#include <math.h>
#include <stdint.h>

// Problem constants
#define BB 2
#define TT 2048
#define DD 1024
#define HH 16
#define MM (BB*TT)          // 4096 rows
#define NQKV 3072
#define NCOMB 3328          // 3072 qkv + 4*64 proj columns (26 * 128)

// ---------------- scratch (device globals; no allocation allowed) ----------------
__device__ __half g_x_hi[(size_t)MM * DD];
__device__ __half g_w_hi[(size_t)NCOMB * DD];      // combined qkv + proj weights
__device__ __half g_w_lo[(size_t)NCOMB * DD];
__device__ __half g_wout_hi[(size_t)DD * DD];
__device__ __half g_wout_lo[(size_t)DD * DD];
__device__ __half g_attn_hi[(size_t)MM * DD];
__device__ __half g_qkv_hi[(size_t)MM * NCOMB];
__device__ __half g_qkv_lo[(size_t)MM * NCOMB];
// read-lines / J-write-lines, fp16 hi only, layout [bh][t][16] (cols 6..15 zero)
__device__ __half g_r6_hi[(size_t)BB * HH * TT * 16];
__device__ __half g_jw_hi[(size_t)BB * HH * TT * 16];

// ---------------- helpers ----------------
__device__ __forceinline__ uint32_t smem_u32(const void* p) {
    uint32_t a;
    asm("{ .reg .u64 t; cvta.to.shared.u64 t, %1; cvt.u32.u64 %0, t; }" : "=r"(a) : "l"(p));
    return a;
}

#define CP_ASYNC16(saddr, gptr) \
    asm volatile("cp.async.cg.shared.global [%0], [%1], 16;" :: "r"(saddr), "l"(gptr))
#define CP_COMMIT() asm volatile("cp.async.commit_group;")
#define CP_WAIT1()  asm volatile("cp.async.wait_group 1;")
#define CP_WAIT0()  asm volatile("cp.async.wait_group 0;")

#define LDSM_X4(r0, r1, r2, r3, addr) \
    asm volatile("ldmatrix.sync.aligned.m8n8.x4.shared.b16 {%0,%1,%2,%3}, [%4];" \
        : "=r"(r0), "=r"(r1), "=r"(r2), "=r"(r3) : "r"(addr))
#define LDSM_X4_T(r0, r1, r2, r3, addr) \
    asm volatile("ldmatrix.sync.aligned.m8n8.x4.trans.shared.b16 {%0,%1,%2,%3}, [%4];" \
        : "=r"(r0), "=r"(r1), "=r"(r2), "=r"(r3) : "r"(addr))

#define MMA16816(d, a, b0v, b1v) \
    asm volatile("mma.sync.aligned.m16n8k16.row.col.f32.f16.f16.f32 " \
        "{%0,%1,%2,%3}, {%4,%5,%6,%7}, {%8,%9}, {%0,%1,%2,%3};" \
        : "+f"((d)[0]), "+f"((d)[1]), "+f"((d)[2]), "+f"((d)[3]) \
        : "r"((a)[0]), "r"((a)[1]), "r"((a)[2]), "r"((a)[3]), "r"(b0v), "r"(b1v))

__device__ __forceinline__ void split1h(float v, __half& h, __half& l) {
    h = __float2half_rn(v);
    l = __float2half_rn(v - __half2float(h));
}
__device__ __forceinline__ void hilo2h(float x, float y, uint32_t& hi, uint32_t& lo) {
    __half hx = __float2half_rn(x), hy = __float2half_rn(y);
    __half2 t(hx, hy);
    hi = *(uint32_t*)&t;
    __half2 u(__float2half_rn(x - __half2float(hx)),
              __float2half_rn(y - __half2float(hy)));
    lo = *(uint32_t*)&u;
}
__device__ __forceinline__ uint32_t pack_h2(float x, float y) {
    __half2 t(__float2half_rn(x), __float2half_rn(y));
    return *(uint32_t*)&t;
}

// ---------------- hi/lo split conversion ----------------
__global__ void split_kernel(const float* __restrict__ src,
                             __half* __restrict__ hi,
                             __half* __restrict__ lo, int n4)
{
    int i = blockIdx.x * blockDim.x + threadIdx.x;
    if (i >= n4) return;
    float4 v = ((const float4*)src)[i];
    __half h0, h1, h2, h3, l0, l1, l2, l3;
    split1h(v.x, h0, l0); split1h(v.y, h1, l1);
    split1h(v.z, h2, l2); split1h(v.w, h3, l3);
    __half2* hp = (__half2*)(hi + (size_t)i * 4);
    __half2* lp = (__half2*)(lo + (size_t)i * 4);
    hp[0] = __half2(h0, h1); hp[1] = __half2(h2, h3);
    lp[0] = __half2(l0, l1); lp[1] = __half2(l2, l3);
}

__global__ void split_hi_kernel(const float* __restrict__ src,
                                __half* __restrict__ hi, int n4)
{
    int i = blockIdx.x * blockDim.x + threadIdx.x;
    if (i >= n4) return;
    float4 v = ((const float4*)src)[i];
    __half2* hp = (__half2*)(hi + (size_t)i * 4);
    hp[0] = __half2(__float2half_rn(v.x), __float2half_rn(v.y));
    hp[1] = __half2(__float2half_rn(v.z), __float2half_rn(v.w));
}

// ---------------- HMMA fp16x2 GEMM ----------------
#define TILE_B   10240                 // 128*40*2 bytes
#define STAGE_B  (3 * TILE_B)          // Ah, Bh, Bl
#define GEMM_SMEM (2 * STAGE_B)        // 61440

__global__ __launch_bounds__(256, 2)
void gemm_mma(const __half* __restrict__ Ah,
              const __half* __restrict__ Bh, const __half* __restrict__ Bl,
              const float* __restrict__ bias, int bias_n, float* __restrict__ Y,
              __half* __restrict__ Yhi, __half* __restrict__ Ylo,
              int N, int K)
{
    extern __shared__ char smem[];
    const uint32_t sbase = smem_u32(smem);
    const int tid = threadIdx.x;
    const int lane = tid & 31;
    const int wid = tid >> 5;
    const int warp_m = wid >> 2;
    const int warp_n = wid & 3;
    const int m0 = blockIdx.y * 128;
    const int n0 = blockIdx.x * 128;

    float acc[4][4][4];
#pragma unroll
    for (int mt = 0; mt < 4; mt++)
#pragma unroll
        for (int nt = 0; nt < 4; nt++)
#pragma unroll
            for (int r = 0; r < 4; r++) acc[mt][nt][r] = 0.f;

    const int u0 = tid * 2;
    const int row_u0 = u0 >> 2, q_u0 = u0 & 3;
    const int row_u1 = (u0 + 1) >> 2, q_u1 = (u0 + 1) & 3;

    auto load_stage = [&](int c, int s) {
        const int kb = c * 32;
        const uint32_t sb = sbase + s * STAGE_B;
        {
            size_t ga = (size_t)(m0 + row_u0) * K + kb + q_u0 * 8;
            size_t gb = (size_t)(n0 + row_u0) * K + kb + q_u0 * 8;
            uint32_t so = sb + (row_u0 * 40 + q_u0 * 8) * 2;
            CP_ASYNC16(so,              Ah + ga);
            CP_ASYNC16(so + TILE_B,     Bh + gb);
            CP_ASYNC16(so + 2 * TILE_B, Bl + gb);
        }
        {
            size_t ga = (size_t)(m0 + row_u1) * K + kb + q_u1 * 8;
            size_t gb = (size_t)(n0 + row_u1) * K + kb + q_u1 * 8;
            uint32_t so = sb + (row_u1 * 40 + q_u1 * 8) * 2;
            CP_ASYNC16(so,              Ah + ga);
            CP_ASYNC16(so + TILE_B,     Bh + gb);
            CP_ASYNC16(so + 2 * TILE_B, Bl + gb);
        }
        CP_COMMIT();
    };

    const int a_mat = lane >> 3, a_r = lane & 7;
    const int a_row_off = (a_mat & 1) * 8 + a_r;
    const int a_col_off = (a_mat >> 1) * 8;
    const int b_row_off = (a_mat >> 1) * 8 + a_r;
    const int b_col_off = (a_mat & 1) * 8;

    const int nc = K >> 5;
    load_stage(0, 0);

    for (int c = 0; c < nc; c++) {
        const int s = c & 1;
        if (c + 1 < nc) {
            load_stage(c + 1, (c + 1) & 1);
            CP_WAIT1();
        } else {
            CP_WAIT0();
        }
        __syncthreads();

        const uint32_t sb = sbase + s * STAGE_B;
#pragma unroll
        for (int ks = 0; ks < 2; ks++) {
            uint32_t ah[4][4];
#pragma unroll
            for (int mt = 0; mt < 4; mt++) {
                int row = warp_m * 64 + mt * 16 + a_row_off;
                int col = ks * 16 + a_col_off;
                uint32_t ad = sb + (row * 40 + col) * 2;
                LDSM_X4(ah[mt][0], ah[mt][1], ah[mt][2], ah[mt][3], ad);
            }
            uint32_t bh[2][4], bl[2][4];
#pragma unroll
            for (int np = 0; np < 2; np++) {
                int nrow = warp_n * 32 + np * 16 + b_row_off;
                int kcol = ks * 16 + b_col_off;
                uint32_t bd = sb + TILE_B + (nrow * 40 + kcol) * 2;
                LDSM_X4(bh[np][0], bh[np][1], bh[np][2], bh[np][3], bd);
                LDSM_X4(bl[np][0], bl[np][1], bl[np][2], bl[np][3], bd + TILE_B);
            }
            // pass 1: Ah.Bh
#pragma unroll
            for (int mt = 0; mt < 4; mt++)
#pragma unroll
                for (int nt = 0; nt < 4; nt++)
                    MMA16816(acc[mt][nt], ah[mt],
                             bh[nt >> 1][(nt & 1) * 2], bh[nt >> 1][(nt & 1) * 2 + 1]);
            // pass 2: Ah.Bl
#pragma unroll
            for (int mt = 0; mt < 4; mt++)
#pragma unroll
                for (int nt = 0; nt < 4; nt++)
                    MMA16816(acc[mt][nt], ah[mt],
                             bl[nt >> 1][(nt & 1) * 2], bl[nt >> 1][(nt & 1) * 2 + 1]);
        }
        __syncthreads();
    }

    // epilogue
#pragma unroll
    for (int mt = 0; mt < 4; mt++) {
        int rbase = m0 + warp_m * 64 + mt * 16 + (lane >> 2);
#pragma unroll
        for (int nt = 0; nt < 4; nt++) {
            int col = n0 + warp_n * 32 + nt * 8 + (lane & 3) * 2;
            float b0 = 0.f, b1 = 0.f;
            if (col < bias_n) { b0 = bias[col]; b1 = bias[col + 1]; }
            float v0 = acc[mt][nt][0] + b0, v1 = acc[mt][nt][1] + b1;
            float v2 = acc[mt][nt][2] + b0, v3 = acc[mt][nt][3] + b1;
            if (Yhi) {
                uint32_t h01, l01, h23, l23;
                hilo2h(v0, v1, h01, l01);
                hilo2h(v2, v3, h23, l23);
                *(uint32_t*)(Yhi + (size_t)rbase * N + col) = h01;
                *(uint32_t*)(Ylo + (size_t)rbase * N + col) = l01;
                *(uint32_t*)(Yhi + (size_t)(rbase + 8) * N + col) = h23;
                *(uint32_t*)(Ylo + (size_t)(rbase + 8) * N + col) = l23;
            } else {
                *(float2*)(Y + (size_t)rbase * N + col) = make_float2(v0, v1);
                *(float2*)(Y + (size_t)(rbase + 8) * N + col) = make_float2(v2, v3);
            }
        }
    }
}

// ---------------- Plücker lines + J6 -> fp16 hi padded ----------------
__device__ __forceinline__ void exterior6(const float p1[4], const float p2[4], float L[6])
{
    L[0] = p1[0]*p2[1] - p1[1]*p2[0];
    L[1] = p1[0]*p2[2] - p1[2]*p2[0];
    L[2] = p1[0]*p2[3] - p1[3]*p2[0];
    L[3] = p1[1]*p2[2] - p1[2]*p2[1];
    L[4] = p1[1]*p2[3] - p1[3]*p2[1];
    L[5] = p1[2]*p2[3] - p1[3]*p2[2];
    float n = sqrtf(L[0]*L[0]+L[1]*L[1]+L[2]*L[2]+L[3]*L[3]+L[4]*L[4]+L[5]*L[5]);
    n = fmaxf(n, 1e-12f);
    float inv = 1.f / n;
#pragma unroll
    for (int i = 0; i < 6; i++) L[i] *= inv;
}

__global__ void lines_kernel(const __half* __restrict__ qh, const __half* __restrict__ ql,
                             __half* __restrict__ r6h, __half* __restrict__ jwh)
{
    int idx = blockIdx.x * blockDim.x + threadIdx.x;
    if (idx >= BB * TT * HH) return;
    int h = idx % HH;
    int t = (idx / HH) % TT;
    int b = idx / (HH * TT);
    int bt = b * TT + t;

    auto projv = [&](int row, int c) -> float {
        size_t o = (size_t)row * NCOMB + 3072 + c;
        return __half2float(qh[o]) + __half2float(ql[o]);
    };

    float p1[4] = {0.f, 0.f, 0.f, 0.f};
    if (t > 0) {
#pragma unroll
        for (int c = 0; c < 4; c++)
            p1[c] = projv(bt - 1, 0 * 64 + h * 4 + c);
    }
    float p2[4], q1[4], q2[4];
#pragma unroll
    for (int c = 0; c < 4; c++) {
        p2[c] = projv(bt,  64 + h * 4 + c);
        q1[c] = projv(bt, 128 + h * 4 + c);
        q2[c] = projv(bt, 192 + h * 4 + c);
    }
    float L[6], Jw[6], R[6];
    exterior6(p1, p2, L);
    Jw[0] =  L[5]; Jw[1] = -L[4]; Jw[2] =  L[3];
    Jw[3] =  L[2]; Jw[4] = -L[1]; Jw[5] =  L[0];
    exterior6(q1, q2, R);

    size_t o = ((size_t)(b * HH + h) * TT + t) * 16;
#pragma unroll
    for (int c = 0; c < 6; c++) {
        jwh[o + c] = __float2half_rn(Jw[c]);
        r6h[o + c] = __float2half_rn(R[c]);
    }
    __half z = __float2half(0.f);
#pragma unroll
    for (int c = 6; c < 16; c++) {
        jwh[o + c] = z; r6h[o + c] = z;
    }
}

// ---------------- flash attention with incidence bias (HMMA fp16) ----------------
// 128-row q tile, 8 warps (16 q-rows each); shared K/V/J double-buffered stages.
// S = Qh.Kh + Qh.Kl (x2); PV = Ph.Vh + Ph.Vl (x2); incidence = r6h.Jh (x1).
// Shift-free softmax (logits bounded), decay via multiplicative recurrence.
#define FL_QS_H   0
#define FL_R6H    18432
#define FL_STAGE0 24576
#define FL_KH 0
#define FL_KL 9216
#define FL_VH 18432
#define FL_VL 27648
#define FL_JH 36864
#define FL_STG 39936
#define FLASH2_SMEM (FL_STAGE0 + 2 * FL_STG)   // 104448

__global__ __launch_bounds__(256, 2)
void flash_hmma(const __half* __restrict__ qkvh,
                const __half* __restrict__ qkvl,
                const __half* __restrict__ r6h_g,
                const __half* __restrict__ jwh_g,
                const float* __restrict__ decay_logits,
                const float* __restrict__ bias_scale,
                __half* __restrict__ oh)
{
    extern __shared__ char smem[];
    const uint32_t sb = smem_u32(smem);
    const int tid = threadIdx.x, lane = tid & 31, w = tid >> 5;   // w: 0..7
    const int qt = (int)gridDim.x - 1 - (int)blockIdx.x;          // heavy CTAs first
    const int bh = blockIdx.y, b = bh >> 4, h = bh & 15;
    const int q0 = qt * 128;
    const int nkt = 2 * qt + 2;       // k-tiles: 0 .. 2qt+1

    const float dec = 1.f / (1.f + __expf(-decay_logits[h]));
    const float logd = __logf(dec);
    const float bsc = bias_scale[h];
    const float d2 = dec * dec, d4 = d2 * d2, d8p = d4 * d4;  // decay^8
    const float dmi = 1.f / dec;                               // decay^-1
    const float dm8 = 1.f / d8p;                               // decay^-8

    // ---- group A: Q hi tile (128 rows) + R6 hi tile ----
#pragma unroll
    for (int i = 0; i < 4; i++) {
        int id = tid + i * 256;
        int row = id >> 3, c = id & 7;
        const __half* src = qkvh + (size_t)(b * TT + q0 + row) * NCOMB + h * 64 + c * 8;
        CP_ASYNC16(sb + FL_QS_H + row * 144 + c * 16, src);
    }
    {
        int row = tid >> 1, hf = tid & 1;
        const __half* src = r6h_g + ((size_t)bh * TT + q0 + row) * 16 + hf * 8;
        CP_ASYNC16(sb + FL_R6H + row * 48 + hf * 16, src);
    }
    CP_COMMIT();

    auto issue_stage = [&](int kt, int s) {
        const int kt0 = kt * 64;
        const uint32_t stg = sb + FL_STAGE0 + s * FL_STG;
#pragma unroll
        for (int i = 0; i < 8; i++) {
            int id = tid + i * 256;
            int arr = id >> 9, rem = id & 511, row = rem >> 3, c = rem & 7;
            size_t off = (size_t)(b * TT + kt0 + row) * NCOMB + h * 64 + c * 8
                       + ((arr & 2) ? 2048 : 1024);
            const __half* src = ((arr & 1) ? qkvl : qkvh) + off;
            uint32_t dbase = (arr == 0) ? FL_KH : (arr == 1) ? FL_KL : (arr == 2) ? FL_VH : FL_VL;
            CP_ASYNC16(stg + dbase + row * 144 + c * 16, src);
        }
        if (tid < 128) {
            int row = tid >> 1, hf = tid & 1;
            const __half* src = jwh_g + ((size_t)bh * TT + kt0 + row) * 16 + hf * 8;
            CP_ASYNC16(stg + FL_JH + row * 48 + hf * 16, src);
        }
        CP_COMMIT();
    };

    issue_stage(0, 0);
    CP_WAIT1();         // Q + R6 done
    __syncthreads();

    const int amat = lane >> 3, ar = lane & 7;
    const int a_row = (amat & 1) * 8 + ar;
    const int a_colu = amat >> 1;
    const int b_row = (amat >> 1) * 8 + ar;
    const int b_colu = amat & 1;

    // preload r6 hi A-frag
    uint32_t r6fh[4];
    {
        uint32_t ad = sb + FL_R6H + (w * 16 + a_row) * 48 + a_colu * 16;
        LDSM_X4(r6fh[0], r6fh[1], r6fh[2], r6fh[3], ad);
    }

    float Oa[8][4];
#pragma unroll
    for (int nt = 0; nt < 8; nt++)
#pragma unroll
        for (int e = 0; e < 4; e++) Oa[nt][e] = 0.f;
    float l0v = 0.f, l1v = 0.f;

    const int r0g = q0 + w * 16 + (lane >> 2);
    const int r1g = r0g + 8;
    const int cb = (lane & 3) * 2;
    const int vkey = (lane & 7) + ((lane >> 3) & 1) * 8;
    const int vdo = (lane >> 4) * 8;

    for (int kb = 0; kb < nkt; kb++) {
        const int s = kb & 1;
        if (kb + 1 < nkt) { issue_stage(kb + 1, s ^ 1); CP_WAIT1(); }
        else              { CP_WAIT0(); }
        __syncthreads();
        const uint32_t stg = sb + FL_STAGE0 + s * FL_STG;

        // ---- incidence acc = r6h . Jh^T (x1) ----
        float ia[8][4];
#pragma unroll
        for (int nt = 0; nt < 8; nt++)
#pragma unroll
            for (int e = 0; e < 4; e++) ia[nt][e] = 0.f;
        {
            uint32_t jh[4][4];
#pragma unroll
            for (int nb = 0; nb < 4; nb++) {
                uint32_t jad = stg + FL_JH + (nb * 16 + b_row) * 48 + b_colu * 16;
                LDSM_X4(jh[nb][0], jh[nb][1], jh[nb][2], jh[nb][3], jad);
            }
#pragma unroll
            for (int nb = 0; nb < 4; nb++) {
                MMA16816(ia[2*nb],   r6fh, jh[nb][0], jh[nb][1]);
                MMA16816(ia[2*nb+1], r6fh, jh[nb][2], jh[nb][3]);
            }
        }

        // ---- S = Qh.Kh + Qh.Kl (x2) ----
        float sa[8][4];
#pragma unroll
        for (int nt = 0; nt < 8; nt++)
#pragma unroll
            for (int e = 0; e < 4; e++) sa[nt][e] = 0.f;
#pragma unroll
        for (int ks = 0; ks < 4; ks++) {
            uint32_t qf_h[4];
            uint32_t qad = sb + FL_QS_H + (w * 16 + a_row) * 144 + (ks * 16 + a_colu * 8) * 2;
            LDSM_X4(qf_h[0], qf_h[1], qf_h[2], qf_h[3], qad);
            uint32_t kh[4][4], kl[4][4];
#pragma unroll
            for (int nb = 0; nb < 4; nb++) {
                uint32_t kad = stg + FL_KH + (nb * 16 + b_row) * 144 + (ks * 16 + b_colu * 8) * 2;
                LDSM_X4(kh[nb][0], kh[nb][1], kh[nb][2], kh[nb][3], kad);
                LDSM_X4(kl[nb][0], kl[nb][1], kl[nb][2], kl[nb][3], kad + 9216);
            }
#pragma unroll
            for (int nb = 0; nb < 4; nb++) {
                MMA16816(sa[2*nb],   qf_h, kh[nb][0], kh[nb][1]);
                MMA16816(sa[2*nb+1], qf_h, kh[nb][2], kh[nb][3]);
            }
#pragma unroll
            for (int nb = 0; nb < 4; nb++) {
                MMA16816(sa[2*nb],   qf_h, kl[nb][0], kl[nb][1]);
                MMA16816(sa[2*nb+1], qf_h, kl[nb][2], kl[nb][3]);
            }
        }

        // ---- scale + bias + mask + shift-free exp ----
        const int kt0 = kb * 64;
        float wr0 = bsc * __expf(logd * (float)(r0g - kt0 - cb));
        float wr1 = wr0 * d8p;
#pragma unroll
        for (int nt = 0; nt < 8; nt++) {
            float w00 = wr0, w01 = wr0 * dmi;
            float w10 = wr1, w11 = wr1 * dmi;
#pragma unroll
            for (int e = 0; e < 4; e++) {
                int rg = (e < 2) ? r0g : r1g;
                int kg = kt0 + nt * 8 + cb + (e & 1);
                float sv = sa[nt][e] * 0.125f;
                int diff = rg - kg;
                if (diff < 0) sv = -1e30f;
                else if (diff > 0) {
                    float wv = (e == 0) ? w00 : (e == 1) ? w01 : (e == 2) ? w10 : w11;
                    sv = fmaf(wv, ia[nt][e], sv);
                }
                float p = __expf(sv);     // exp(-1e30) -> 0
                sa[nt][e] = p;
                if (e < 2) l0v += p; else l1v += p;
            }
            wr0 *= dm8;
            wr1 *= dm8;
        }

        // ---- O += Ph.Vh + Ph.Vl (x2) ----
#pragma unroll
        for (int j = 0; j < 4; j++) {
            uint32_t ph[4];
            ph[0] = pack_h2(sa[2*j][0],   sa[2*j][1]);
            ph[1] = pack_h2(sa[2*j][2],   sa[2*j][3]);
            ph[2] = pack_h2(sa[2*j+1][0], sa[2*j+1][1]);
            ph[3] = pack_h2(sa[2*j+1][2], sa[2*j+1][3]);
            uint32_t vh[4][4], vl[4][4];
#pragma unroll
            for (int nb = 0; nb < 4; nb++) {
                uint32_t vad = stg + FL_VH + (16 * j + vkey) * 144 + (nb * 16 + vdo) * 2;
                LDSM_X4_T(vh[nb][0], vh[nb][1], vh[nb][2], vh[nb][3], vad);
                LDSM_X4_T(vl[nb][0], vl[nb][1], vl[nb][2], vl[nb][3], vad + 9216);
            }
#pragma unroll
            for (int nb = 0; nb < 4; nb++) {
                MMA16816(Oa[2*nb],   ph, vh[nb][0], vh[nb][1]);
                MMA16816(Oa[2*nb+1], ph, vh[nb][2], vh[nb][3]);
            }
#pragma unroll
            for (int nb = 0; nb < 4; nb++) {
                MMA16816(Oa[2*nb],   ph, vl[nb][0], vl[nb][1]);
                MMA16816(Oa[2*nb+1], ph, vl[nb][2], vl[nb][3]);
            }
        }
        __syncthreads();
    }

    // ---- final denominator reduce + normalize + write ----
    l0v += __shfl_xor_sync(0xffffffffu, l0v, 1);
    l0v += __shfl_xor_sync(0xffffffffu, l0v, 2);
    l1v += __shfl_xor_sync(0xffffffffu, l1v, 1);
    l1v += __shfl_xor_sync(0xffffffffu, l1v, 2);
    const float inv0 = 1.f / l0v, inv1 = 1.f / l1v;
#pragma unroll
    for (int nt = 0; nt < 8; nt++) {
        int dcol = nt * 8 + cb;
        size_t o0 = (size_t)(b * TT + r0g) * DD + h * 64 + dcol;
        size_t o1 = (size_t)(b * TT + r1g) * DD + h * 64 + dcol;
        *(uint32_t*)(oh + o0) = pack_h2(Oa[nt][0] * inv0, Oa[nt][1] * inv0);
        *(uint32_t*)(oh + o1) = pack_h2(Oa[nt][2] * inv1, Oa[nt][3] * inv1);
    }
}

// ---------------- launch ----------------
extern "C" void kernel_launch(void* const* d_in, const int* in_sizes, int n_in,
                              void* d_out, int out_size)
{
    const float* x      = (const float*)d_in[0];
    const float* w_qkv  = (const float*)d_in[1];
    const float* b_qkv  = (const float*)d_in[2];
    const float* w1w    = (const float*)d_in[3];
    const float* w2w    = (const float*)d_in[4];
    const float* w1r    = (const float*)d_in[5];
    const float* w2r    = (const float*)d_in[6];
    const float* w_out  = (const float*)d_in[7];
    const float* b_out  = (const float*)d_in[8];
    const float* dl     = (const float*)d_in[9];
    const float* bs     = (const float*)d_in[10];

    __half *xh, *wh, *wl, *woh, *wol, *ath;
    __half *qkvh, *qkvl, *r6h, *jwh;
    cudaGetSymbolAddress((void**)&xh,  g_x_hi);
    cudaGetSymbolAddress((void**)&wh,  g_w_hi);
    cudaGetSymbolAddress((void**)&wl,  g_w_lo);
    cudaGetSymbolAddress((void**)&woh, g_wout_hi);
    cudaGetSymbolAddress((void**)&wol, g_wout_lo);
    cudaGetSymbolAddress((void**)&ath, g_attn_hi);
    cudaGetSymbolAddress((void**)&qkvh, g_qkv_hi);
    cudaGetSymbolAddress((void**)&qkvl, g_qkv_lo);
    cudaGetSymbolAddress((void**)&r6h, g_r6_hi);
    cudaGetSymbolAddress((void**)&jwh, g_jw_hi);

    cudaFuncSetAttribute(gemm_mma, cudaFuncAttributeMaxDynamicSharedMemorySize, GEMM_SMEM);
    cudaFuncSetAttribute(flash_hmma, cudaFuncAttributeMaxDynamicSharedMemorySize, FLASH2_SMEM);

    // 0. hi/lo splits: x (hi only); combined weight [w_qkv | w1w..w2r]; w_out
    {
        int n4;
        n4 = (MM * DD) / 4;
        split_hi_kernel<<<(n4 + 255) / 256, 256>>>(x, xh, n4);
        n4 = (NQKV * DD) / 4;
        split_kernel<<<(n4 + 255) / 256, 256>>>(w_qkv, wh, wl, n4);
        n4 = (64 * DD) / 4;   // 16384
        split_kernel<<<(n4 + 255) / 256, 256>>>(w1w, wh + (size_t)3072 * DD, wl + (size_t)3072 * DD, n4);
        split_kernel<<<(n4 + 255) / 256, 256>>>(w2w, wh + (size_t)3136 * DD, wl + (size_t)3136 * DD, n4);
        split_kernel<<<(n4 + 255) / 256, 256>>>(w1r, wh + (size_t)3200 * DD, wl + (size_t)3200 * DD, n4);
        split_kernel<<<(n4 + 255) / 256, 256>>>(w2r, wh + (size_t)3264 * DD, wl + (size_t)3264 * DD, n4);
        n4 = (DD * DD) / 4;
        split_kernel<<<(n4 + 255) / 256, 256>>>(w_out, woh, wol, n4);
    }
    // 1. fused QKV + proj GEMM -> fp16 hi/lo [M, 3328]
    {
        dim3 grid(NCOMB / 128, MM / 128);
        gemm_mma<<<grid, 256, GEMM_SMEM>>>(xh, wh, wl, b_qkv, NQKV,
                                           nullptr, qkvh, qkvl, NCOMB, DD);
    }
    // 2. Plücker lines + J6 from proj columns (hi+lo reconstruct) -> fp16 hi
    {
        int n = BB * TT * HH;
        lines_kernel<<<(n + 255) / 256, 256>>>(qkvh, qkvl, r6h, jwh);
    }
    // 3. flash attention (HMMA, 128-row q tile, 8 warps) -> attn hi
    {
        dim3 grid(TT / 128, BB * HH);
        flash_hmma<<<grid, 256, FLASH2_SMEM>>>(qkvh, qkvl, r6h, jwh, dl, bs, ath);
    }
    // 4. output projection (fp16x2, fp32 out + bias)
    {
        dim3 grid(DD / 128, MM / 128);
        gemm_mma<<<grid, 256, GEMM_SMEM>>>(ath, woh, wol, b_out, DD,
                                           (float*)d_out, nullptr, nullptr, DD, DD);
    }
}

// round 15
// speedup vs baseline: 1.1598x; 1.1598x over previous
#include <cuda_runtime.h>
#include <cuda_fp16.h>
#include <math.h>
#include <stdint.h>

// Problem constants
#define BB 2
#define TT 2048
#define DD 1024
#define HH 16
#define MM (BB*TT)          // 4096 rows
#define NQKV 3072
#define NCOMB 3328          // 3072 qkv + 4*64 proj columns (26 * 128)

// ---------------- scratch (device globals; no allocation allowed) ----------------
__device__ __half g_x_hi[(size_t)MM * DD];
__device__ __half g_w_hi[(size_t)NCOMB * DD];      // combined qkv + proj weights
__device__ __half g_w_lo[(size_t)NCOMB * DD];
__device__ __half g_wout_hi[(size_t)DD * DD];
__device__ __half g_wout_lo[(size_t)DD * DD];
__device__ __half g_attn_hi[(size_t)MM * DD];
__device__ __half g_qkv_hi[(size_t)MM * NCOMB];
__device__ __half g_qkv_lo[(size_t)MM * NCOMB];    // used only for proj-column reconstruct
// read-lines / J-write-lines, fp16 hi only, layout [bh][t][16] (cols 6..15 zero)
__device__ __half g_r6_hi[(size_t)BB * HH * TT * 16];
__device__ __half g_jw_hi[(size_t)BB * HH * TT * 16];

// ---------------- helpers ----------------
__device__ __forceinline__ uint32_t smem_u32(const void* p) {
    uint32_t a;
    asm("{ .reg .u64 t; cvta.to.shared.u64 t, %1; cvt.u32.u64 %0, t; }" : "=r"(a) : "l"(p));
    return a;
}

#define CP_ASYNC16(saddr, gptr) \
    asm volatile("cp.async.cg.shared.global [%0], [%1], 16;" :: "r"(saddr), "l"(gptr))
#define CP_COMMIT() asm volatile("cp.async.commit_group;")
#define CP_WAIT1()  asm volatile("cp.async.wait_group 1;")
#define CP_WAIT0()  asm volatile("cp.async.wait_group 0;")

#define LDSM_X4(r0, r1, r2, r3, addr) \
    asm volatile("ldmatrix.sync.aligned.m8n8.x4.shared.b16 {%0,%1,%2,%3}, [%4];" \
        : "=r"(r0), "=r"(r1), "=r"(r2), "=r"(r3) : "r"(addr))
#define LDSM_X4_T(r0, r1, r2, r3, addr) \
    asm volatile("ldmatrix.sync.aligned.m8n8.x4.trans.shared.b16 {%0,%1,%2,%3}, [%4];" \
        : "=r"(r0), "=r"(r1), "=r"(r2), "=r"(r3) : "r"(addr))

#define MMA16816(d, a, b0v, b1v) \
    asm volatile("mma.sync.aligned.m16n8k16.row.col.f32.f16.f16.f32 " \
        "{%0,%1,%2,%3}, {%4,%5,%6,%7}, {%8,%9}, {%0,%1,%2,%3};" \
        : "+f"((d)[0]), "+f"((d)[1]), "+f"((d)[2]), "+f"((d)[3]) \
        : "r"((a)[0]), "r"((a)[1]), "r"((a)[2]), "r"((a)[3]), "r"(b0v), "r"(b1v))

__device__ __forceinline__ void split1h(float v, __half& h, __half& l) {
    h = __float2half_rn(v);
    l = __float2half_rn(v - __half2float(h));
}
__device__ __forceinline__ void hilo2h(float x, float y, uint32_t& hi, uint32_t& lo) {
    __half hx = __float2half_rn(x), hy = __float2half_rn(y);
    __half2 t(hx, hy);
    hi = *(uint32_t*)&t;
    __half2 u(__float2half_rn(x - __half2float(hx)),
              __float2half_rn(y - __half2float(hy)));
    lo = *(uint32_t*)&u;
}
__device__ __forceinline__ uint32_t pack_h2(float x, float y) {
    __half2 t(__float2half_rn(x), __float2half_rn(y));
    return *(uint32_t*)&t;
}

// ---------------- hi/lo split conversion ----------------
__global__ void split_kernel(const float* __restrict__ src,
                             __half* __restrict__ hi,
                             __half* __restrict__ lo, int n4)
{
    int i = blockIdx.x * blockDim.x + threadIdx.x;
    if (i >= n4) return;
    float4 v = ((const float4*)src)[i];
    __half h0, h1, h2, h3, l0, l1, l2, l3;
    split1h(v.x, h0, l0); split1h(v.y, h1, l1);
    split1h(v.z, h2, l2); split1h(v.w, h3, l3);
    __half2* hp = (__half2*)(hi + (size_t)i * 4);
    __half2* lp = (__half2*)(lo + (size_t)i * 4);
    hp[0] = __half2(h0, h1); hp[1] = __half2(h2, h3);
    lp[0] = __half2(l0, l1); lp[1] = __half2(l2, l3);
}

__global__ void split_hi_kernel(const float* __restrict__ src,
                                __half* __restrict__ hi, int n4)
{
    int i = blockIdx.x * blockDim.x + threadIdx.x;
    if (i >= n4) return;
    float4 v = ((const float4*)src)[i];
    __half2* hp = (__half2*)(hi + (size_t)i * 4);
    hp[0] = __half2(__float2half_rn(v.x), __float2half_rn(v.y));
    hp[1] = __half2(__float2half_rn(v.z), __float2half_rn(v.w));
}

// ---------------- HMMA fp16x2 GEMM ----------------
#define TILE_B   10240                 // 128*40*2 bytes
#define STAGE_B  (3 * TILE_B)          // Ah, Bh, Bl
#define GEMM_SMEM (2 * STAGE_B)        // 61440

__global__ __launch_bounds__(256, 2)
void gemm_mma(const __half* __restrict__ Ah,
              const __half* __restrict__ Bh, const __half* __restrict__ Bl,
              const float* __restrict__ bias, int bias_n, float* __restrict__ Y,
              __half* __restrict__ Yhi, __half* __restrict__ Ylo,
              int N, int K)
{
    extern __shared__ char smem[];
    const uint32_t sbase = smem_u32(smem);
    const int tid = threadIdx.x;
    const int lane = tid & 31;
    const int wid = tid >> 5;
    const int warp_m = wid >> 2;
    const int warp_n = wid & 3;
    const int m0 = blockIdx.y * 128;
    const int n0 = blockIdx.x * 128;

    float acc[4][4][4];
#pragma unroll
    for (int mt = 0; mt < 4; mt++)
#pragma unroll
        for (int nt = 0; nt < 4; nt++)
#pragma unroll
            for (int r = 0; r < 4; r++) acc[mt][nt][r] = 0.f;

    const int u0 = tid * 2;
    const int row_u0 = u0 >> 2, q_u0 = u0 & 3;
    const int row_u1 = (u0 + 1) >> 2, q_u1 = (u0 + 1) & 3;

    auto load_stage = [&](int c, int s) {
        const int kb = c * 32;
        const uint32_t sb = sbase + s * STAGE_B;
        {
            size_t ga = (size_t)(m0 + row_u0) * K + kb + q_u0 * 8;
            size_t gb = (size_t)(n0 + row_u0) * K + kb + q_u0 * 8;
            uint32_t so = sb + (row_u0 * 40 + q_u0 * 8) * 2;
            CP_ASYNC16(so,              Ah + ga);
            CP_ASYNC16(so + TILE_B,     Bh + gb);
            CP_ASYNC16(so + 2 * TILE_B, Bl + gb);
        }
        {
            size_t ga = (size_t)(m0 + row_u1) * K + kb + q_u1 * 8;
            size_t gb = (size_t)(n0 + row_u1) * K + kb + q_u1 * 8;
            uint32_t so = sb + (row_u1 * 40 + q_u1 * 8) * 2;
            CP_ASYNC16(so,              Ah + ga);
            CP_ASYNC16(so + TILE_B,     Bh + gb);
            CP_ASYNC16(so + 2 * TILE_B, Bl + gb);
        }
        CP_COMMIT();
    };

    const int a_mat = lane >> 3, a_r = lane & 7;
    const int a_row_off = (a_mat & 1) * 8 + a_r;
    const int a_col_off = (a_mat >> 1) * 8;
    const int b_row_off = (a_mat >> 1) * 8 + a_r;
    const int b_col_off = (a_mat & 1) * 8;

    const int nc = K >> 5;
    load_stage(0, 0);

    for (int c = 0; c < nc; c++) {
        const int s = c & 1;
        if (c + 1 < nc) {
            load_stage(c + 1, (c + 1) & 1);
            CP_WAIT1();
        } else {
            CP_WAIT0();
        }
        __syncthreads();

        const uint32_t sb = sbase + s * STAGE_B;
#pragma unroll
        for (int ks = 0; ks < 2; ks++) {
            uint32_t ah[4][4];
#pragma unroll
            for (int mt = 0; mt < 4; mt++) {
                int row = warp_m * 64 + mt * 16 + a_row_off;
                int col = ks * 16 + a_col_off;
                uint32_t ad = sb + (row * 40 + col) * 2;
                LDSM_X4(ah[mt][0], ah[mt][1], ah[mt][2], ah[mt][3], ad);
            }
            uint32_t bh[2][4], bl[2][4];
#pragma unroll
            for (int np = 0; np < 2; np++) {
                int nrow = warp_n * 32 + np * 16 + b_row_off;
                int kcol = ks * 16 + b_col_off;
                uint32_t bd = sb + TILE_B + (nrow * 40 + kcol) * 2;
                LDSM_X4(bh[np][0], bh[np][1], bh[np][2], bh[np][3], bd);
                LDSM_X4(bl[np][0], bl[np][1], bl[np][2], bl[np][3], bd + TILE_B);
            }
            // pass 1: Ah.Bh
#pragma unroll
            for (int mt = 0; mt < 4; mt++)
#pragma unroll
                for (int nt = 0; nt < 4; nt++)
                    MMA16816(acc[mt][nt], ah[mt],
                             bh[nt >> 1][(nt & 1) * 2], bh[nt >> 1][(nt & 1) * 2 + 1]);
            // pass 2: Ah.Bl
#pragma unroll
            for (int mt = 0; mt < 4; mt++)
#pragma unroll
                for (int nt = 0; nt < 4; nt++)
                    MMA16816(acc[mt][nt], ah[mt],
                             bl[nt >> 1][(nt & 1) * 2], bl[nt >> 1][(nt & 1) * 2 + 1]);
        }
        __syncthreads();
    }

    // epilogue
#pragma unroll
    for (int mt = 0; mt < 4; mt++) {
        int rbase = m0 + warp_m * 64 + mt * 16 + (lane >> 2);
#pragma unroll
        for (int nt = 0; nt < 4; nt++) {
            int col = n0 + warp_n * 32 + nt * 8 + (lane & 3) * 2;
            float b0 = 0.f, b1 = 0.f;
            if (col < bias_n) { b0 = bias[col]; b1 = bias[col + 1]; }
            float v0 = acc[mt][nt][0] + b0, v1 = acc[mt][nt][1] + b1;
            float v2 = acc[mt][nt][2] + b0, v3 = acc[mt][nt][3] + b1;
            if (Yhi) {
                uint32_t h01, l01, h23, l23;
                hilo2h(v0, v1, h01, l01);
                hilo2h(v2, v3, h23, l23);
                *(uint32_t*)(Yhi + (size_t)rbase * N + col) = h01;
                *(uint32_t*)(Ylo + (size_t)rbase * N + col) = l01;
                *(uint32_t*)(Yhi + (size_t)(rbase + 8) * N + col) = h23;
                *(uint32_t*)(Ylo + (size_t)(rbase + 8) * N + col) = l23;
            } else {
                *(float2*)(Y + (size_t)rbase * N + col) = make_float2(v0, v1);
                *(float2*)(Y + (size_t)(rbase + 8) * N + col) = make_float2(v2, v3);
            }
        }
    }
}

// ---------------- Plücker lines + J6 -> fp16 hi padded ----------------
__device__ __forceinline__ void exterior6(const float p1[4], const float p2[4], float L[6])
{
    L[0] = p1[0]*p2[1] - p1[1]*p2[0];
    L[1] = p1[0]*p2[2] - p1[2]*p2[0];
    L[2] = p1[0]*p2[3] - p1[3]*p2[0];
    L[3] = p1[1]*p2[2] - p1[2]*p2[1];
    L[4] = p1[1]*p2[3] - p1[3]*p2[1];
    L[5] = p1[2]*p2[3] - p1[3]*p2[2];
    float n = sqrtf(L[0]*L[0]+L[1]*L[1]+L[2]*L[2]+L[3]*L[3]+L[4]*L[4]+L[5]*L[5]);
    n = fmaxf(n, 1e-12f);
    float inv = 1.f / n;
#pragma unroll
    for (int i = 0; i < 6; i++) L[i] *= inv;
}

__global__ void lines_kernel(const __half* __restrict__ qh, const __half* __restrict__ ql,
                             __half* __restrict__ r6h, __half* __restrict__ jwh)
{
    int idx = blockIdx.x * blockDim.x + threadIdx.x;
    if (idx >= BB * TT * HH) return;
    int h = idx % HH;
    int t = (idx / HH) % TT;
    int b = idx / (HH * TT);
    int bt = b * TT + t;

    auto projv = [&](int row, int c) -> float {
        size_t o = (size_t)row * NCOMB + 3072 + c;
        return __half2float(qh[o]) + __half2float(ql[o]);
    };

    float p1[4] = {0.f, 0.f, 0.f, 0.f};
    if (t > 0) {
#pragma unroll
        for (int c = 0; c < 4; c++)
            p1[c] = projv(bt - 1, 0 * 64 + h * 4 + c);
    }
    float p2[4], q1[4], q2[4];
#pragma unroll
    for (int c = 0; c < 4; c++) {
        p2[c] = projv(bt,  64 + h * 4 + c);
        q1[c] = projv(bt, 128 + h * 4 + c);
        q2[c] = projv(bt, 192 + h * 4 + c);
    }
    float L[6], Jw[6], R[6];
    exterior6(p1, p2, L);
    Jw[0] =  L[5]; Jw[1] = -L[4]; Jw[2] =  L[3];
    Jw[3] =  L[2]; Jw[4] = -L[1]; Jw[5] =  L[0];
    exterior6(q1, q2, R);

    size_t o = ((size_t)(b * HH + h) * TT + t) * 16;
#pragma unroll
    for (int c = 0; c < 6; c++) {
        jwh[o + c] = __float2half_rn(Jw[c]);
        r6h[o + c] = __float2half_rn(R[c]);
    }
    __half z = __float2half(0.f);
#pragma unroll
    for (int c = 6; c < 16; c++) {
        jwh[o + c] = z; r6h[o + c] = z;
    }
}

// ---------------- flash attention with incidence bias (HMMA fp16) ----------------
// R13 structure (64-row q tile, 128 threads) with hi-only K and V:
// S = Qh.Kh (x1); PV = Ph.Vh (x1); incidence = r6h.Jh (x1).
// Stage smem halves -> 55.3 KB total -> 4 CTAs/SM.
#define FL_QS_H   0
#define FL_R6H    9216
#define FL_STAGE0 12288
#define FL_KH 0
#define FL_VH 9216
#define FL_JH 18432
#define FL_STG 21504
#define FLASH2_SMEM (FL_STAGE0 + 2 * FL_STG)   // 55296

__global__ __launch_bounds__(128, 4)
void flash_hmma(const __half* __restrict__ qkvh,
                const __half* __restrict__ r6h_g,
                const __half* __restrict__ jwh_g,
                const float* __restrict__ decay_logits,
                const float* __restrict__ bias_scale,
                __half* __restrict__ oh)
{
    extern __shared__ char smem[];
    const uint32_t sb = smem_u32(smem);
    const int tid = threadIdx.x, lane = tid & 31, w = tid >> 5;
    const int qb = (int)gridDim.x - 1 - (int)blockIdx.x;   // heavy CTAs first
    const int bh = blockIdx.y, b = bh >> 4, h = bh & 15;
    const int q0 = qb * 64;

    const float dec = 1.f / (1.f + __expf(-decay_logits[h]));
    const float logd = __logf(dec);
    const float bsc = bias_scale[h];
    const float d2 = dec * dec, d4 = d2 * d2, d8p = d4 * d4;  // decay^8
    const float dmi = 1.f / dec;                               // decay^-1
    const float dm8 = 1.f / d8p;                               // decay^-8

    // ---- group A: Q hi tile + R6 hi tile ----
#pragma unroll
    for (int i = 0; i < 4; i++) {
        int id = tid + i * 128;
        int row = id >> 3, c = id & 7;
        const __half* src = qkvh + (size_t)(b * TT + q0 + row) * NCOMB + h * 64 + c * 8;
        CP_ASYNC16(sb + FL_QS_H + row * 144 + c * 16, src);
    }
    {
        int row = tid >> 1, hf = tid & 1;
        const __half* src = r6h_g + ((size_t)bh * TT + q0 + row) * 16 + hf * 8;
        CP_ASYNC16(sb + FL_R6H + row * 48 + hf * 16, src);
    }
    CP_COMMIT();

    auto issue_stage = [&](int kt, int s) {
        const int kt0 = kt * 64;
        const uint32_t stg = sb + FL_STAGE0 + s * FL_STG;
#pragma unroll
        for (int i = 0; i < 8; i++) {
            int id = tid + i * 128;              // 0..1023: K hi (512), V hi (512)
            int arr = id >> 9, rem = id & 511, row = rem >> 3, c = rem & 7;
            size_t off = (size_t)(b * TT + kt0 + row) * NCOMB + h * 64 + c * 8
                       + (arr ? 2048 : 1024);
            CP_ASYNC16(stg + (arr ? FL_VH : FL_KH) + row * 144 + c * 16, qkvh + off);
        }
        {
            int row = tid >> 1, hf = tid & 1;
            const __half* src = jwh_g + ((size_t)bh * TT + kt0 + row) * 16 + hf * 8;
            CP_ASYNC16(stg + FL_JH + row * 48 + hf * 16, src);
        }
        CP_COMMIT();
    };

    issue_stage(0, 0);
    CP_WAIT1();         // Q + R6 done
    __syncthreads();

    const int amat = lane >> 3, ar = lane & 7;
    const int a_row = (amat & 1) * 8 + ar;
    const int a_colu = amat >> 1;
    const int b_row = (amat >> 1) * 8 + ar;
    const int b_colu = amat & 1;

    // preload r6 hi A-frag (rank-6 incidence, k16 zero-padded)
    uint32_t r6fh[4];
    {
        uint32_t ad = sb + FL_R6H + (w * 16 + a_row) * 48 + a_colu * 16;
        LDSM_X4(r6fh[0], r6fh[1], r6fh[2], r6fh[3], ad);
    }

    float Oa[8][4];
#pragma unroll
    for (int nt = 0; nt < 8; nt++)
#pragma unroll
        for (int e = 0; e < 4; e++) Oa[nt][e] = 0.f;
    float l0v = 0.f, l1v = 0.f;     // un-shifted softmax denominators

    const int r0g = q0 + w * 16 + (lane >> 2);
    const int r1g = r0g + 8;
    const int cb = (lane & 3) * 2;
    const int vkey = (lane & 7) + ((lane >> 3) & 1) * 8;
    const int vdo = (lane >> 4) * 8;

    for (int kb = 0; kb <= qb; kb++) {
        const int s = kb & 1;
        if (kb + 1 <= qb) { issue_stage(kb + 1, s ^ 1); CP_WAIT1(); }
        else              { CP_WAIT0(); }
        __syncthreads();
        const uint32_t stg = sb + FL_STAGE0 + s * FL_STG;

        // ---- incidence acc = r6h . Jh^T (x1) ----
        float ia[8][4];
#pragma unroll
        for (int nt = 0; nt < 8; nt++)
#pragma unroll
            for (int e = 0; e < 4; e++) ia[nt][e] = 0.f;
        {
            uint32_t jh[4][4];
#pragma unroll
            for (int nb = 0; nb < 4; nb++) {
                uint32_t jad = stg + FL_JH + (nb * 16 + b_row) * 48 + b_colu * 16;
                LDSM_X4(jh[nb][0], jh[nb][1], jh[nb][2], jh[nb][3], jad);
            }
#pragma unroll
            for (int nb = 0; nb < 4; nb++) {
                MMA16816(ia[2*nb],   r6fh, jh[nb][0], jh[nb][1]);
                MMA16816(ia[2*nb+1], r6fh, jh[nb][2], jh[nb][3]);
            }
        }

        // ---- S = Qh.Kh (x1) ----
        float sa[8][4];
#pragma unroll
        for (int nt = 0; nt < 8; nt++)
#pragma unroll
            for (int e = 0; e < 4; e++) sa[nt][e] = 0.f;
#pragma unroll
        for (int ks = 0; ks < 4; ks++) {
            uint32_t qf_h[4];
            uint32_t qad = sb + FL_QS_H + (w * 16 + a_row) * 144 + (ks * 16 + a_colu * 8) * 2;
            LDSM_X4(qf_h[0], qf_h[1], qf_h[2], qf_h[3], qad);
            uint32_t kh[4][4];
#pragma unroll
            for (int nb = 0; nb < 4; nb++) {
                uint32_t kad = stg + FL_KH + (nb * 16 + b_row) * 144 + (ks * 16 + b_colu * 8) * 2;
                LDSM_X4(kh[nb][0], kh[nb][1], kh[nb][2], kh[nb][3], kad);
            }
#pragma unroll
            for (int nb = 0; nb < 4; nb++) {
                MMA16816(sa[2*nb],   qf_h, kh[nb][0], kh[nb][1]);
                MMA16816(sa[2*nb+1], qf_h, kh[nb][2], kh[nb][3]);
            }
        }

        // ---- scale + bias + mask + shift-free exp ----
        const int kt0 = kb * 64;
        float wr0 = bsc * __expf(logd * (float)(r0g - kt0 - cb));
        float wr1 = wr0 * d8p;
#pragma unroll
        for (int nt = 0; nt < 8; nt++) {
            float w00 = wr0, w01 = wr0 * dmi;
            float w10 = wr1, w11 = wr1 * dmi;
#pragma unroll
            for (int e = 0; e < 4; e++) {
                int rg = (e < 2) ? r0g : r1g;
                int kg = kt0 + nt * 8 + cb + (e & 1);
                float sv = sa[nt][e] * 0.125f;
                int diff = rg - kg;
                if (diff < 0) sv = -1e30f;
                else if (diff > 0) {
                    float wv = (e == 0) ? w00 : (e == 1) ? w01 : (e == 2) ? w10 : w11;
                    sv = fmaf(wv, ia[nt][e], sv);
                }
                float p = __expf(sv);     // exp(-1e30) -> 0
                sa[nt][e] = p;
                if (e < 2) l0v += p; else l1v += p;
            }
            wr0 *= dm8;
            wr1 *= dm8;
        }

        // ---- O += Ph.Vh (x1) ----
#pragma unroll
        for (int j = 0; j < 4; j++) {
            uint32_t ph[4];
            ph[0] = pack_h2(sa[2*j][0],   sa[2*j][1]);
            ph[1] = pack_h2(sa[2*j][2],   sa[2*j][3]);
            ph[2] = pack_h2(sa[2*j+1][0], sa[2*j+1][1]);
            ph[3] = pack_h2(sa[2*j+1][2], sa[2*j+1][3]);
            uint32_t vh[4][4];
#pragma unroll
            for (int nb = 0; nb < 4; nb++) {
                uint32_t vad = stg + FL_VH + (16 * j + vkey) * 144 + (nb * 16 + vdo) * 2;
                LDSM_X4_T(vh[nb][0], vh[nb][1], vh[nb][2], vh[nb][3], vad);
            }
#pragma unroll
            for (int nb = 0; nb < 4; nb++) {
                MMA16816(Oa[2*nb],   ph, vh[nb][0], vh[nb][1]);
                MMA16816(Oa[2*nb+1], ph, vh[nb][2], vh[nb][3]);
            }
        }
        __syncthreads();
    }

    // ---- final denominator reduce (once) + normalize + write ----
    l0v += __shfl_xor_sync(0xffffffffu, l0v, 1);
    l0v += __shfl_xor_sync(0xffffffffu, l0v, 2);
    l1v += __shfl_xor_sync(0xffffffffu, l1v, 1);
    l1v += __shfl_xor_sync(0xffffffffu, l1v, 2);
    const float inv0 = 1.f / l0v, inv1 = 1.f / l1v;
#pragma unroll
    for (int nt = 0; nt < 8; nt++) {
        int dcol = nt * 8 + cb;
        size_t o0 = (size_t)(b * TT + r0g) * DD + h * 64 + dcol;
        size_t o1 = (size_t)(b * TT + r1g) * DD + h * 64 + dcol;
        *(uint32_t*)(oh + o0) = pack_h2(Oa[nt][0] * inv0, Oa[nt][1] * inv0);
        *(uint32_t*)(oh + o1) = pack_h2(Oa[nt][2] * inv1, Oa[nt][3] * inv1);
    }
}

// ---------------- launch ----------------
extern "C" void kernel_launch(void* const* d_in, const int* in_sizes, int n_in,
                              void* d_out, int out_size)
{
    const float* x      = (const float*)d_in[0];
    const float* w_qkv  = (const float*)d_in[1];
    const float* b_qkv  = (const float*)d_in[2];
    const float* w1w    = (const float*)d_in[3];
    const float* w2w    = (const float*)d_in[4];
    const float* w1r    = (const float*)d_in[5];
    const float* w2r    = (const float*)d_in[6];
    const float* w_out  = (const float*)d_in[7];
    const float* b_out  = (const float*)d_in[8];
    const float* dl     = (const float*)d_in[9];
    const float* bs     = (const float*)d_in[10];

    __half *xh, *wh, *wl, *woh, *wol, *ath;
    __half *qkvh, *qkvl, *r6h, *jwh;
    cudaGetSymbolAddress((void**)&xh,  g_x_hi);
    cudaGetSymbolAddress((void**)&wh,  g_w_hi);
    cudaGetSymbolAddress((void**)&wl,  g_w_lo);
    cudaGetSymbolAddress((void**)&woh, g_wout_hi);
    cudaGetSymbolAddress((void**)&wol, g_wout_lo);
    cudaGetSymbolAddress((void**)&ath, g_attn_hi);
    cudaGetSymbolAddress((void**)&qkvh, g_qkv_hi);
    cudaGetSymbolAddress((void**)&qkvl, g_qkv_lo);
    cudaGetSymbolAddress((void**)&r6h, g_r6_hi);
    cudaGetSymbolAddress((void**)&jwh, g_jw_hi);

    cudaFuncSetAttribute(gemm_mma, cudaFuncAttributeMaxDynamicSharedMemorySize, GEMM_SMEM);
    cudaFuncSetAttribute(flash_hmma, cudaFuncAttributeMaxDynamicSharedMemorySize, FLASH2_SMEM);

    // 0. hi/lo splits: x (hi only); combined weight [w_qkv | w1w..w2r]; w_out
    {
        int n4;
        n4 = (MM * DD) / 4;
        split_hi_kernel<<<(n4 + 255) / 256, 256>>>(x, xh, n4);
        n4 = (NQKV * DD) / 4;
        split_kernel<<<(n4 + 255) / 256, 256>>>(w_qkv, wh, wl, n4);
        n4 = (64 * DD) / 4;   // 16384
        split_kernel<<<(n4 + 255) / 256, 256>>>(w1w, wh + (size_t)3072 * DD, wl + (size_t)3072 * DD, n4);
        split_kernel<<<(n4 + 255) / 256, 256>>>(w2w, wh + (size_t)3136 * DD, wl + (size_t)3136 * DD, n4);
        split_kernel<<<(n4 + 255) / 256, 256>>>(w1r, wh + (size_t)3200 * DD, wl + (size_t)3200 * DD, n4);
        split_kernel<<<(n4 + 255) / 256, 256>>>(w2r, wh + (size_t)3264 * DD, wl + (size_t)3264 * DD, n4);
        n4 = (DD * DD) / 4;
        split_kernel<<<(n4 + 255) / 256, 256>>>(w_out, woh, wol, n4);
    }
    // 1. fused QKV + proj GEMM -> fp16 hi/lo [M, 3328]
    {
        dim3 grid(NCOMB / 128, MM / 128);
        gemm_mma<<<grid, 256, GEMM_SMEM>>>(xh, wh, wl, b_qkv, NQKV,
                                           nullptr, qkvh, qkvl, NCOMB, DD);
    }
    // 2. Plücker lines + J6 from proj columns (hi+lo reconstruct) -> fp16 hi
    {
        int n = BB * TT * HH;
        lines_kernel<<<(n + 255) / 256, 256>>>(qkvh, qkvl, r6h, jwh);
    }
    // 3. flash attention (HMMA fp16 hi-only, shift-free softmax) -> attn hi
    {
        dim3 grid(TT / 64, BB * HH);
        flash_hmma<<<grid, 128, FLASH2_SMEM>>>(qkvh, r6h, jwh, dl, bs, ath);
    }
    // 4. output projection (fp16x2, fp32 out + bias)
    {
        dim3 grid(DD / 128, MM / 128);
        gemm_mma<<<grid, 256, GEMM_SMEM>>>(ath, woh, wol, b_out, DD,
                                           (float*)d_out, nullptr, nullptr, DD, DD);
    }
}